// round 11
// baseline (speedup 1.0000x reference)
#include <cuda_runtime.h>
#include <cuda_fp16.h>
#include <cstdint>

// Problem constants (fixed by setup_inputs: N=32768, D=512, F=64)
#define D_DIM  512
#define F_DIM  64
#define TILE_M 128
#define NTH    256
#define NSLAB  16
#define STAGES 3
#define NMAIN  256          // main CTAs
#define NPREP  40           // producer CTAs
#define GRID   (NMAIN + NPREP)

// Stage = x1 slab (16 KB) + M slab (4 KB)
#define STG_SZ   20480
#define M_IN_STG 16384
#define AUX_OFF  (STAGES * STG_SZ)        // 61440
#define SMEM_BYTES (AUX_OFF + 512)

// Scratch (device globals: allocation-free rule)
__device__ uint16_t g_Mh[D_DIM * F_DIM];   // fp16 M[k][f], written slab-by-slab
__device__ float    g_c[F_DIM];
__device__ int      g_slab_done[NSLAB];
__device__ int      g_c_flag;

// ---------------------------------------------------------------------------
// helpers
// ---------------------------------------------------------------------------
__device__ __forceinline__ unsigned smem_u32(const void* p) {
    return (unsigned)__cvta_generic_to_shared(p);
}
__device__ __forceinline__ void cp_async16(unsigned saddr, const void* g) {
    asm volatile("cp.async.cg.shared.global [%0], [%1], 16;\n" :: "r"(saddr), "l"(g));
}
#define CP_COMMIT() asm volatile("cp.async.commit_group;\n")
#define CP_WAIT(n)  asm volatile("cp.async.wait_group %0;\n" :: "n"(n))

__device__ __forceinline__ uint32_t cvt_h2(float2 e) {
    uint32_t r;
    asm("cvt.rn.f16x2.f32 %0, %1, %2;" : "=r"(r) : "f"(e.y), "f"(e.x));
    return r;
}
__device__ __forceinline__ float2 lds64(uint32_t a) {
    float2 v;
    asm volatile("ld.shared.v2.f32 {%0, %1}, [%2];" : "=f"(v.x), "=f"(v.y) : "r"(a));
    return v;
}

#define LDMX4T(r0, r1, r2, r3, a) \
    asm volatile("ldmatrix.sync.aligned.m8n8.x4.trans.shared.b16 {%0,%1,%2,%3}, [%4];" \
                 : "=r"(r0), "=r"(r1), "=r"(r2), "=r"(r3) : "r"(a))

#define MMA16816(d, a0, a1, a2, a3, b0, b1) \
    asm volatile("mma.sync.aligned.m16n8k16.row.col.f32.f16.f16.f32 " \
                 "{%0,%1,%2,%3}, {%4,%5,%6,%7}, {%8,%9}, {%0,%1,%2,%3};" \
                 : "+f"((d)[0]), "+f"((d)[1]), "+f"((d)[2]), "+f"((d)[3]) \
                 : "r"(a0), "r"(a1), "r"(a2), "r"(a3), "r"(b0), "r"(b1))

// ---------------------------------------------------------------------------
__global__ void init_flags_kernel() {
    if (threadIdx.x < NSLAB) g_slab_done[threadIdx.x] = 0;
    if (threadIdx.x == NSLAB) g_c_flag = 0;
}

// ---------------------------------------------------------------------------
// Fused kernel: CTAs [0,256) consume (HMMA GEMM + epilogue), CTAs [256,296)
// produce M slab-by-slab from W. W-stream and x1-stream overlap on DRAM.
// ---------------------------------------------------------------------------
__global__ void __launch_bounds__(NTH, 2) fused_kernel(
    const float* __restrict__ x1, const float* __restrict__ x2,
    const float* __restrict__ V,  const float* __restrict__ W,
    const float* __restrict__ b,  const float* __restrict__ U,
    float* __restrict__ out)
{
    extern __shared__ char smem[];
    uint32_t sb = smem_u32(smem);
    int tid = threadIdx.x, warp = tid >> 5, lane = tid & 31;

    if (blockIdx.x >= NMAIN) {
        // ================= PREP role =================
        int pid = blockIdx.x - NMAIN;             // 0..39
        float* s_x2 = (float*)smem;
        s_x2[tid] = x2[tid];
        s_x2[tid + 256] = x2[tid + 256];
        __syncthreads();
        const float4* x2v = reinterpret_cast<const float4*>(s_x2);
        int wg = pid * 8 + warp;                  // 0..319

        for (int s = 0; s < NSLAB; s++) {
            for (int grp = wg; grp < 512; grp += NPREP * 8) {
                int j0 = grp * 4;                 // local row in slab (0..2047)
                int f = j0 >> 5;
                int dloc = j0 & 31;               // multiple of 4
                const float4* wr0 = reinterpret_cast<const float4*>(
                    W + ((size_t)f * D_DIM + s * 32 + dloc) * D_DIM);

                float4 wv[4][4];
                #pragma unroll
                for (int r = 0; r < 4; r++)
                    #pragma unroll
                    for (int it = 0; it < 4; it++)
                        wv[r][it] = __ldcs(wr0 + r * 128 + lane + it * 32);

                float a[4] = {0.f, 0.f, 0.f, 0.f};
                #pragma unroll
                for (int it = 0; it < 4; it++) {
                    float4 xv = x2v[lane + it * 32];
                    #pragma unroll
                    for (int r = 0; r < 4; r++)
                        a[r] += wv[r][it].x * xv.x + wv[r][it].y * xv.y
                              + wv[r][it].z * xv.z + wv[r][it].w * xv.w;
                }
                #pragma unroll
                for (int o = 16; o; o >>= 1)
                    #pragma unroll
                    for (int r = 0; r < 4; r++)
                        a[r] += __shfl_xor_sync(0xffffffffu, a[r], o);

                if (lane == 0) {
                    #pragma unroll
                    for (int r = 0; r < 4; r++) {
                        int d = s * 32 + dloc + r;
                        float v = a[r] + V[(size_t)f * (2 * D_DIM) + d];
                        __half hv = __float2half_rn(v);
                        g_Mh[d * F_DIM + f] = *reinterpret_cast<uint16_t*>(&hv);
                    }
                    __threadfence();
                }
            }
            __syncthreads();
            if (tid == 0) atomicAdd(&g_slab_done[s], 1);
        }

        if (pid == 0) {
            // c[f] = V2[f]·x2 + b[f]; 8 warps x 8 f
            #pragma unroll
            for (int j = 0; j < 8; j++) {
                int f = warp + j * 8;
                const float4* vrow = reinterpret_cast<const float4*>(
                    V + (size_t)f * (2 * D_DIM) + D_DIM);
                float acc = 0.f;
                #pragma unroll
                for (int it = 0; it < 4; it++) {
                    float4 vv = vrow[lane + it * 32];
                    float4 xv = x2v[lane + it * 32];
                    acc += vv.x * xv.x + vv.y * xv.y + vv.z * xv.z + vv.w * xv.w;
                }
                #pragma unroll
                for (int o = 16; o; o >>= 1) acc += __shfl_xor_sync(0xffffffffu, acc, o);
                if (lane == 0) { g_c[f] = acc + b[f]; __threadfence(); }
            }
            __syncthreads();
            if (tid == 0) { __threadfence(); atomicExch(&g_c_flag, 1); }
        }
        return;
    }

    // ================= MAIN role =================
    float* sc = (float*)(smem + AUX_OFF);
    float* sU = (float*)(smem + AUX_OFF + 256);
    int base = blockIdx.x * TILE_M;

    auto wait_slab = [&](int s) {
        if (tid == 0) {
            volatile int* p = &g_slab_done[s];
            while (*p < NPREP) __nanosleep(64);
            __threadfence();
        }
        __syncthreads();
    };

    // stage issuer: x1 slab (1024 x 16B, 4/thread) + M slab (256 x 16B, 1/thread)
    auto issue_stage = [&](int s) {
        int buf = s % STAGES;
        uint32_t sbase = sb + buf * STG_SZ;
        const float* src = x1 + (size_t)base * D_DIM + s * 32;
        #pragma unroll
        for (int j = 0; j < 4; j++) {
            int i = j * NTH + tid;
            int row = i >> 3, c = i & 7;
            cp_async16(sbase + row * 128 + ((c ^ (row & 7)) * 16),
                       src + (size_t)row * D_DIM + c * 4);
        }
        int kl = tid >> 3, nb = tid & 7;
        cp_async16(sbase + M_IN_STG + kl * 128 + ((nb ^ (kl & 7)) * 16),
                   g_Mh + (s * 32 + kl) * F_DIM + nb * 8);
    };

    wait_slab(0); issue_stage(0); CP_COMMIT();
    wait_slab(1); issue_stage(1); CP_COMMIT();

    int g = lane >> 2, tig = lane & 3;
    int klane = lane & 15, nsel = lane >> 4;
    uint32_t rowoff = (uint32_t)(klane * 128);
    uint32_t colp[4];
    #pragma unroll
    for (int p = 0; p < 4; p++)
        colp[p] = (uint32_t)(((2 * p + nsel) * 16) ^ ((klane & 7) * 16));

    float acc[8][4];
    #pragma unroll
    for (int nt = 0; nt < 8; nt++)
        #pragma unroll
        for (int q = 0; q < 4; q++) acc[nt][q] = 0.f;

    uint32_t aoffs[2][2];
    #pragma unroll
    for (int h = 0; h < 2; h++)
        #pragma unroll
        for (int j = 0; j < 2; j++) {
            int R = warp * 16 + g + 8 * h;
            int c = j * 2 + (tig >> 1);
            aoffs[h][j] = (uint32_t)((R << 7) | (c << 1) | (tig & 1));
        }

    for (int s = 0; s < NSLAB; s++) {
        int buf = s % STAGES;
        CP_WAIT(1);
        __syncthreads();

        if (s + 2 < NSLAB) { wait_slab(s + 2); issue_stage(s + 2); }
        CP_COMMIT();

        uint32_t abase = sb + buf * STG_SZ;
        uint32_t mstg = abase + M_IN_STG;
        #pragma unroll
        for (int ksub = 0; ksub < 2; ksub++) {
            uint32_t Ah[4];
            #pragma unroll
            for (int h = 0; h < 2; h++)
                #pragma unroll
                for (int j = 0; j < 2; j++) {
                    uint32_t enc = aoffs[h][j];
                    int R = enc >> 7;
                    int c = ((enc >> 1) & 0x3F) + ksub * 4;
                    int lo8 = (enc & 1) * 8;
                    uint32_t addr = abase + (R << 7)
                                  + (uint32_t)(((c ^ (R & 7)) * 16) + lo8);
                    Ah[h + 2 * j] = cvt_h2(lds64(addr));
                }

            uint32_t bbase = mstg + (uint32_t)(ksub * 16 * 128) + rowoff;
            #pragma unroll
            for (int p = 0; p < 4; p++) {
                uint32_t h0, h1, h2, h3;
                LDMX4T(h0, h1, h2, h3, bbase + colp[p]);
                MMA16816(acc[2 * p],     Ah[0], Ah[1], Ah[2], Ah[3], h0, h1);
                MMA16816(acc[2 * p + 1], Ah[0], Ah[1], Ah[2], Ah[3], h2, h3);
            }
        }
    }

    // epilogue: need g_c -> wait for producer's c flag
    if (tid == 0) {
        volatile int* p = &g_c_flag;
        while (*p == 0) __nanosleep(64);
        __threadfence();
    }
    __syncthreads();
    if (tid < F_DIM) { sc[tid] = g_c[tid]; sU[tid] = U[tid]; }
    __syncthreads();

    int rowBase = base + warp * 16;
    #pragma unroll
    for (int h = 0; h < 2; h++) {
        float s = 0.f, num = 0.f;
        #pragma unroll
        for (int nt = 0; nt < 8; nt++) {
            int f0 = nt * 8 + tig * 2;
            float v0 = acc[nt][2 * h]     + sc[f0];
            float v1 = acc[nt][2 * h + 1] + sc[f0 + 1];
            s   += fabsf(v0) + fabsf(v1);
            num += fmaxf(v0, 0.f) * sU[f0] + fmaxf(v1, 0.f) * sU[f0 + 1];
        }
        s   += __shfl_xor_sync(0xffffffffu, s, 1);
        s   += __shfl_xor_sync(0xffffffffu, s, 2);
        num += __shfl_xor_sync(0xffffffffu, num, 1);
        num += __shfl_xor_sync(0xffffffffu, num, 2);
        if (tig == 0)
            out[rowBase + g + 8 * h] = num / fmaxf(s, 1e-12f);
    }
}

// ---------------------------------------------------------------------------
// launch
// ---------------------------------------------------------------------------
extern "C" void kernel_launch(void* const* d_in, const int* in_sizes, int n_in,
                              void* d_out, int out_size)
{
    const float* x1 = (const float*)d_in[0];   // (N, 512)
    const float* x2 = (const float*)d_in[1];   // (1, 512)
    const float* V  = (const float*)d_in[2];   // (64, 1024)
    const float* W  = (const float*)d_in[3];   // (64, 512, 512)
    const float* b  = (const float*)d_in[4];   // (64,)
    const float* U  = (const float*)d_in[5];   // (64, 1)
    float* out = (float*)d_out;                // (N, 1)

    cudaFuncSetAttribute(fused_kernel, cudaFuncAttributeMaxDynamicSharedMemorySize,
                         SMEM_BYTES);

    init_flags_kernel<<<1, 32>>>();
    fused_kernel<<<GRID, NTH, SMEM_BYTES>>>(x1, x2, V, W, b, U, out);
}

// round 12
// speedup vs baseline: 2.5309x; 2.5309x over previous
#include <cuda_runtime.h>
#include <cuda_fp16.h>
#include <cstdint>

// Problem constants (fixed by setup_inputs: N=32768, D=512, F=64)
#define D_DIM  512
#define F_DIM  64
#define TILE_M 64           // rows per CTA (4 warps x 16 rows)
#define NTH    128
#define NSLAB  16           // 16 slabs of 32 k
#define STAGES 4

// Stage = x1 slab (8 KB) + M slab (4 KB)
#define X_BYTES  8192
#define STG_SZ   12288
#define AUX_OFF  (STAGES * STG_SZ)        // 49152
#define SMEM_BYTES (AUX_OFF + 512)

// Scratch (device globals: allocation-free rule)
__device__ uint16_t g_Mh[D_DIM * F_DIM];   // fp16 M[k][f]
__device__ float    g_c[F_DIM];            // c[f] = V2[f]·x2 + b[f]

// ---------------------------------------------------------------------------
// helpers
// ---------------------------------------------------------------------------
__device__ __forceinline__ unsigned smem_u32(const void* p) {
    return (unsigned)__cvta_generic_to_shared(p);
}
__device__ __forceinline__ void cp_async16(unsigned saddr, const void* g) {
    asm volatile("cp.async.cg.shared.global [%0], [%1], 16;\n" :: "r"(saddr), "l"(g));
}
#define CP_COMMIT() asm volatile("cp.async.commit_group;\n")
#define CP_WAIT(n)  asm volatile("cp.async.wait_group %0;\n" :: "n"(n))

// float2 -> packed half2 (lo16 = e.x, hi16 = e.y)
__device__ __forceinline__ uint32_t cvt_h2(float2 e) {
    uint32_t r;
    asm("cvt.rn.f16x2.f32 %0, %1, %2;" : "=r"(r) : "f"(e.y), "f"(e.x));
    return r;
}
__device__ __forceinline__ float2 lds64(uint32_t a) {
    float2 v;
    asm volatile("ld.shared.v2.f32 {%0, %1}, [%2];" : "=f"(v.x), "=f"(v.y) : "r"(a));
    return v;
}

#define LDMX4T(r0, r1, r2, r3, a) \
    asm volatile("ldmatrix.sync.aligned.m8n8.x4.trans.shared.b16 {%0,%1,%2,%3}, [%4];" \
                 : "=r"(r0), "=r"(r1), "=r"(r2), "=r"(r3) : "r"(a))

#define MMA16816(d, a0, a1, a2, a3, b0, b1) \
    asm volatile("mma.sync.aligned.m16n8k16.row.col.f32.f16.f16.f32 " \
                 "{%0,%1,%2,%3}, {%4,%5,%6,%7}, {%8,%9}, {%0,%1,%2,%3};" \
                 : "+f"((d)[0]), "+f"((d)[1]), "+f"((d)[2]), "+f"((d)[3]) \
                 : "r"(a0), "r"(a1), "r"(a2), "r"(a3), "r"(b0), "r"(b1))

// ---------------------------------------------------------------------------
// Kernel A: stream W once -> M[k][f] fp16 in global; also c[f]
// (R10-proven: ~5 TB/s with high warp count)
// ---------------------------------------------------------------------------
__global__ void __launch_bounds__(256) prep_kernel(
    const float* __restrict__ x2, const float* __restrict__ V,
    const float* __restrict__ W, const float* __restrict__ b)
{
    __shared__ float s_x2[D_DIM];
    int tid = threadIdx.x;
    for (int i = tid; i < D_DIM; i += blockDim.x) s_x2[i] = x2[i];
    __syncthreads();

    int lane = tid & 31;
    int warp = tid >> 5;
    const float4* x2v = reinterpret_cast<const float4*>(s_x2);

    if (blockIdx.x < 1024) {
        int r0 = blockIdx.x * 32 + warp * 4;   // rows r0..r0+3 of 32768

        float4 wv[4][4];
        #pragma unroll
        for (int r = 0; r < 4; r++) {
            const float4* wr =
                reinterpret_cast<const float4*>(W + (size_t)(r0 + r) * D_DIM);
            #pragma unroll
            for (int it = 0; it < 4; it++) wv[r][it] = __ldcs(&wr[lane + it * 32]);
        }

        float a[4] = {0.f, 0.f, 0.f, 0.f};
        #pragma unroll
        for (int it = 0; it < 4; it++) {
            float4 xv = x2v[lane + it * 32];
            #pragma unroll
            for (int r = 0; r < 4; r++) {
                a[r] += wv[r][it].x * xv.x + wv[r][it].y * xv.y
                      + wv[r][it].z * xv.z + wv[r][it].w * xv.w;
            }
        }
        #pragma unroll
        for (int o = 16; o; o >>= 1) {
            #pragma unroll
            for (int r = 0; r < 4; r++)
                a[r] += __shfl_xor_sync(0xffffffffu, a[r], o);
        }
        if (lane == 0) {
            #pragma unroll
            for (int r = 0; r < 4; r++) {
                int rr = r0 + r;
                int f = rr >> 9, d = rr & 511;
                float v = a[r] + V[(size_t)f * (2 * D_DIM) + d];
                __half hv = __float2half_rn(v);
                g_Mh[d * F_DIM + f] = *reinterpret_cast<uint16_t*>(&hv);
            }
        }
    } else {
        #pragma unroll
        for (int j = 0; j < 8; j++) {
            int f = warp + j * 8;
            const float4* vrow =
                reinterpret_cast<const float4*>(V + (size_t)f * (2 * D_DIM) + D_DIM);
            float acc = 0.f;
            #pragma unroll
            for (int it = 0; it < 4; it++) {
                float4 vv = vrow[lane + it * 32];
                float4 xv = x2v[lane + it * 32];
                acc += vv.x * xv.x + vv.y * xv.y + vv.z * xv.z + vv.w * xv.w;
            }
            #pragma unroll
            for (int o = 16; o; o >>= 1) acc += __shfl_xor_sync(0xffffffffu, acc, o);
            if (lane == 0) g_c[f] = acc + b[f];
        }
    }
}

// ---------------------------------------------------------------------------
// Kernel B: fp16 HMMA GEMM + fused L1-norm/relu/@U, 4-stage cp.async.
// grid=512, 128 threads (4 warps x 16 rows), ~4 CTAs/SM (49KB smem each).
// Each stage carries both the x1 slab and the M slab (M re-read via L2).
// Stage s+2 issued BEFORE waiting on stage s.
// ---------------------------------------------------------------------------
__global__ void __launch_bounds__(NTH) main_kernel(
    const float* __restrict__ x1, const float* __restrict__ U,
    float* __restrict__ out)
{
    extern __shared__ char smem[];
    uint32_t sb = smem_u32(smem);
    float* sc = (float*)(smem + AUX_OFF);
    float* sU = (float*)(smem + AUX_OFF + 256);

    int tid = threadIdx.x, warp = tid >> 5, lane = tid & 31;
    int base = blockIdx.x * TILE_M;

    // stage issuer: x1 slab (512 x 16B, 4/thread) + M slab (256 x 16B, 2/thread)
    auto issue_stage = [&](int s) {
        int buf = s & (STAGES - 1);
        uint32_t sbase = sb + buf * STG_SZ;
        const float* src = x1 + (size_t)base * D_DIM + s * 32;
        #pragma unroll
        for (int j = 0; j < 4; j++) {
            int i = j * NTH + tid;
            int row = i >> 3, c = i & 7;
            cp_async16(sbase + row * 128 + ((c ^ (row & 7)) * 16),
                       src + (size_t)row * D_DIM + c * 4);
        }
        #pragma unroll
        for (int j = 0; j < 2; j++) {
            int i = j * NTH + tid;
            int kl = i >> 3, nb = i & 7;
            cp_async16(sbase + X_BYTES + kl * 128 + ((nb ^ (kl & 7)) * 16),
                       g_Mh + (s * 32 + kl) * F_DIM + nb * 8);
        }
    };

    issue_stage(0);
    CP_COMMIT();
    issue_stage(1);
    CP_COMMIT();
    if (tid < F_DIM) { sc[tid] = g_c[tid]; sU[tid] = U[tid]; }

    int g = lane >> 2, tig = lane & 3;
    int klane = lane & 15, nsel = lane >> 4;
    uint32_t rowoff = (uint32_t)(klane * 128);
    uint32_t colp[4];
    #pragma unroll
    for (int p = 0; p < 4; p++)
        colp[p] = (uint32_t)(((2 * p + nsel) * 16) ^ ((klane & 7) * 16));

    float acc[8][4];
    #pragma unroll
    for (int nt = 0; nt < 8; nt++)
        #pragma unroll
        for (int q = 0; q < 4; q++) acc[nt][q] = 0.f;

    // A-frag address parts: R = row in tile, c = 16B chunk (before ksub add)
    uint32_t aoffs[2][2];
    #pragma unroll
    for (int h = 0; h < 2; h++)
        #pragma unroll
        for (int j = 0; j < 2; j++) {
            int R = warp * 16 + g + 8 * h;
            int c = j * 2 + (tig >> 1);
            aoffs[h][j] = (uint32_t)((R << 7) | (c << 1) | (tig & 1));
        }

    for (int s = 0; s < NSLAB; s++) {
        int buf = s & (STAGES - 1);
        // issue stage s+2 FIRST (buffer (s+2)%4 freed: all warps passed the
        // iter s-1 sync => stage s-2 fully consumed), then wait on stage s
        if (s + 2 < NSLAB) issue_stage(s + 2);
        CP_COMMIT();
        CP_WAIT(2);
        __syncthreads();

        uint32_t abase = sb + buf * STG_SZ;
        uint32_t mbase = abase + X_BYTES;
        #pragma unroll
        for (int ksub = 0; ksub < 2; ksub++) {
            uint32_t Ah[4];
            #pragma unroll
            for (int h = 0; h < 2; h++)
                #pragma unroll
                for (int j = 0; j < 2; j++) {
                    uint32_t enc = aoffs[h][j];
                    int R = enc >> 7;
                    int c = ((enc >> 1) & 0x3F) + ksub * 4;
                    int lo8 = (enc & 1) * 8;
                    uint32_t addr = abase + (R << 7)
                                  + (uint32_t)(((c ^ (R & 7)) * 16) + lo8);
                    Ah[h + 2 * j] = cvt_h2(lds64(addr));
                }

            uint32_t bbase = mbase + (uint32_t)(ksub * 16 * 128) + rowoff;
            #pragma unroll
            for (int p = 0; p < 4; p++) {
                uint32_t h0, h1, h2, h3;
                LDMX4T(h0, h1, h2, h3, bbase + colp[p]);
                MMA16816(acc[2 * p],     Ah[0], Ah[1], Ah[2], Ah[3], h0, h1);
                MMA16816(acc[2 * p + 1], Ah[0], Ah[1], Ah[2], Ah[3], h2, h3);
            }
        }
    }

    // epilogue: rows g and g+8; 4 tig-lanes hold the 64 f values of each row
    int rowBase = base + warp * 16;
    #pragma unroll
    for (int h = 0; h < 2; h++) {
        float s = 0.f, num = 0.f;
        #pragma unroll
        for (int nt = 0; nt < 8; nt++) {
            int f0 = nt * 8 + tig * 2;
            float v0 = acc[nt][2 * h]     + sc[f0];
            float v1 = acc[nt][2 * h + 1] + sc[f0 + 1];
            s   += fabsf(v0) + fabsf(v1);
            num += fmaxf(v0, 0.f) * sU[f0] + fmaxf(v1, 0.f) * sU[f0 + 1];
        }
        s   += __shfl_xor_sync(0xffffffffu, s, 1);
        s   += __shfl_xor_sync(0xffffffffu, s, 2);
        num += __shfl_xor_sync(0xffffffffu, num, 1);
        num += __shfl_xor_sync(0xffffffffu, num, 2);
        if (tig == 0)
            out[rowBase + g + 8 * h] = num / fmaxf(s, 1e-12f);
    }
}

// ---------------------------------------------------------------------------
// launch
// ---------------------------------------------------------------------------
extern "C" void kernel_launch(void* const* d_in, const int* in_sizes, int n_in,
                              void* d_out, int out_size)
{
    const float* x1 = (const float*)d_in[0];   // (N, 512)
    const float* x2 = (const float*)d_in[1];   // (1, 512)
    const float* V  = (const float*)d_in[2];   // (64, 1024)
    const float* W  = (const float*)d_in[3];   // (64, 512, 512)
    const float* b  = (const float*)d_in[4];   // (64,)
    const float* U  = (const float*)d_in[5];   // (64, 1)
    float* out = (float*)d_out;                // (N, 1)

    int N = in_sizes[0] / D_DIM;               // 32768

    cudaFuncSetAttribute(main_kernel, cudaFuncAttributeMaxDynamicSharedMemorySize,
                         SMEM_BYTES);

    prep_kernel<<<1024 + 1, 256>>>(x2, V, W, b);
    main_kernel<<<N / TILE_M, NTH, SMEM_BYTES>>>(x1, U, out);
}